// round 13
// baseline (speedup 1.0000x reference)
#include <cuda_runtime.h>
#include <math.h>
#include <stdint.h>

#define B_   4
#define L_   2048
#define DX_  1024
#define H_   16
#define DK_  64
#define HD_  1024      // H*DK
#define EPS_ 1e-5f

// ---------------- scratch (device globals; no allocation allowed) ----------------
__device__ float g_Qs[(size_t)B_ * L_ * HD_];
__device__ float g_Ks[(size_t)B_ * L_ * HD_];
__device__ float g_Vs[(size_t)B_ * L_ * HD_];
__device__ float g_AO[(size_t)B_ * L_ * HD_];
__device__ float g_X [(size_t)B_ * L_ * DX_];
__device__ float g_rWq[(size_t)DX_ * HD_];   // tf32-rounded weights, [K][N] layout
__device__ float g_rWk[(size_t)DX_ * HD_];
__device__ float g_rWv[(size_t)DX_ * HD_];
__device__ float g_rWo[(size_t)HD_ * DX_];
__device__ float g_part[(size_t)B_ * H_ * 16 * L_];  // (b*16+h, k-tile, row): expsum partial

// ---------------- tf32 / cp.async helpers ----------------------------------------
__device__ __forceinline__ unsigned f2tf(float x) {
    unsigned r; asm("cvt.rna.tf32.f32 %0, %1;" : "=r"(r) : "f"(x)); return r;
}
__device__ __forceinline__ float rndtf(float x) { return __uint_as_float(f2tf(x)); }

__device__ __forceinline__ void cp16(void* s, const void* g) {
    unsigned a = (unsigned)__cvta_generic_to_shared(s);
    asm volatile("cp.async.cg.shared.global [%0], [%1], 16;" :: "r"(a), "l"(g));
}
__device__ __forceinline__ void cpcommit() {
    asm volatile("cp.async.commit_group;" ::: "memory");
}
__device__ __forceinline__ void cpwait0() {
    asm volatile("cp.async.wait_group 0;" ::: "memory");
}

__device__ __forceinline__ void mma8(float* d, const unsigned* a, const unsigned* b) {
    asm volatile(
        "mma.sync.aligned.m16n8k8.row.col.f32.tf32.tf32.f32 "
        "{%0,%1,%2,%3},{%4,%5,%6,%7},{%8,%9},{%0,%1,%2,%3};"
        : "+f"(d[0]), "+f"(d[1]), "+f"(d[2]), "+f"(d[3])
        : "r"(a[0]), "r"(a[1]), "r"(a[2]), "r"(a[3]), "r"(b[0]), "r"(b[1]));
}

// ---------------- pre-round weights to tf32 --------------------------------------
__global__ __launch_bounds__(256) void round_tf32(
    const float4* __restrict__ in, float4* __restrict__ out, int n4)
{
    int i = blockIdx.x * blockDim.x + threadIdx.x;
    if (i < n4) {
        float4 v = in[i];
        v.x = rndtf(v.x); v.y = rndtf(v.y); v.z = rndtf(v.z); v.w = rndtf(v.w);
        out[i] = v;
    }
}

// ================= TF32 SGEMM: C[M,N] = A[M,K] @ B[K,N] + bias ===================
// A is RAW fp32 (rounded to tf32 in-register at fragment load); B is pre-rounded.
// BK=32, double buffered, dynamic smem.
#define GA_S 36
#define GB_S 136
#define SG_SMEM ((2 * 128 * GA_S + 2 * 32 * GB_S) * 4)

template<bool ROUND_OUT>
__global__ __launch_bounds__(256, 2) void sgemm_tf32(
    const float* __restrict__ A, const float* __restrict__ Bm,
    const float* __restrict__ bias, float* __restrict__ C,
    int M, int N, int K)
{
    extern __shared__ unsigned smg[];
    unsigned (*As)[128][GA_S] = (unsigned(*)[128][GA_S])smg;
    unsigned (*Bs)[32][GB_S]  = (unsigned(*)[32][GB_S])(smg + 2 * 128 * GA_S);

    const int tid  = threadIdx.x;
    const int lane = tid & 31, warp = tid >> 5;
    const int wr = warp >> 1, wc = warp & 1;
    const int gm = lane >> 2, kq = lane & 3;

    const float* Ab = A  + (size_t)(blockIdx.y * 128) * K;
    const float* Bb = Bm + blockIdx.x * 128;
    const int arow = tid >> 1,  acol = (tid & 1) * 16;
    const int brow = tid >> 3,  bcol = (tid & 7) * 16;

    float acc[2][8][4];
#pragma unroll
    for (int i = 0; i < 2; i++)
#pragma unroll
        for (int j = 0; j < 8; j++)
#pragma unroll
            for (int r = 0; r < 4; r++) acc[i][j][r] = 0.f;

    auto load = [&](int buf, int k0) {
#pragma unroll
        for (int u = 0; u < 4; u++)
            cp16(&As[buf][arow][acol + u * 4], Ab + (size_t)arow * K + k0 + acol + u * 4);
#pragma unroll
        for (int u = 0; u < 4; u++)
            cp16(&Bs[buf][brow][bcol + u * 4], Bb + (size_t)(k0 + brow) * N + bcol + u * 4);
    };

    load(0, 0); cpcommit();
    int buf = 0;
    for (int k0 = 0; k0 < K; k0 += 32) {
        cpwait0();
        __syncthreads();
        if (k0 + 32 < K) { load(buf ^ 1, k0 + 32); cpcommit(); }
#pragma unroll
        for (int kk = 0; kk < 32; kk += 8) {
            unsigned af[2][4], bf[8][2];
#pragma unroll
            for (int i = 0; i < 2; i++) {
                const int mb = wr * 32 + i * 16;
                af[i][0] = f2tf(__uint_as_float(As[buf][mb + gm    ][kk + kq]));
                af[i][1] = f2tf(__uint_as_float(As[buf][mb + gm + 8][kk + kq]));
                af[i][2] = f2tf(__uint_as_float(As[buf][mb + gm    ][kk + kq + 4]));
                af[i][3] = f2tf(__uint_as_float(As[buf][mb + gm + 8][kk + kq + 4]));
            }
#pragma unroll
            for (int j = 0; j < 8; j++) {
                const int nb = wc * 64 + j * 8;
                bf[j][0] = Bs[buf][kk + kq    ][nb + gm];
                bf[j][1] = Bs[buf][kk + kq + 4][nb + gm];
            }
#pragma unroll
            for (int i = 0; i < 2; i++)
#pragma unroll
                for (int j = 0; j < 8; j++) mma8(acc[i][j], af[i], bf[j]);
        }
        __syncthreads();
        buf ^= 1;
    }

#pragma unroll
    for (int i = 0; i < 2; i++)
#pragma unroll
        for (int j = 0; j < 8; j++) {
            const int row = blockIdx.y * 128 + wr * 32 + i * 16 + gm;
            const int col = blockIdx.x * 128 + wc * 64 + j * 8 + kq * 2;
            float2 bv = *(const float2*)(bias + col);
            float2 o0, o1;
            o0.x = acc[i][j][0] + bv.x; o0.y = acc[i][j][1] + bv.y;
            o1.x = acc[i][j][2] + bv.x; o1.y = acc[i][j][3] + bv.y;
            if (ROUND_OUT) {
                o0.x = rndtf(o0.x); o0.y = rndtf(o0.y);
                o1.x = rndtf(o1.x); o1.y = rndtf(o1.y);
            }
            *(float2*)(C + (size_t)row * N + col)       = o0;
            *(float2*)(C + (size_t)(row + 8) * N + col) = o1;
        }
}

// ===== scores: e = exp((Qh@Kh^T)/8) masked->0; writes e + per-tile row expsums ====
#define SCS 68
__global__ __launch_bounds__(256, 2) void scores_tf32(
    const float* __restrict__ Qs, const float* __restrict__ Ks,
    const unsigned char* __restrict__ mask, float* __restrict__ att,
    float* __restrict__ part)
{
    extern __shared__ unsigned sm[];
    unsigned (*Qt)[SCS] = (unsigned(*)[SCS])sm;
    unsigned (*Kt)[SCS] = (unsigned(*)[SCS])(sm + 128 * SCS);
    unsigned char* msk = (unsigned char*)sm;     // reused after mainloop
    __shared__ float ps[2][128];

    const int tid  = threadIdx.x;
    const int lane = tid & 31, warp = tid >> 5;
    const int wr = warp >> 1, wc = warp & 1;
    const int gm = lane >> 2, kq = lane & 3;
    const int bh = blockIdx.z;                  // b*16 + h
    const int b = bh >> 4, h = bh & 15;
    const int q0 = blockIdx.y * 128, n0 = blockIdx.x * 128;

    const float* Qb = Qs + (size_t)b * L_ * HD_ + (size_t)h * DK_;
    const float* Kb = Ks + (size_t)b * L_ * HD_ + (size_t)h * DK_;
    const int lrow = tid >> 1, lcb = (tid & 1) * 32;

#pragma unroll
    for (int u = 0; u < 8; u++) {
        cp16(&Qt[lrow][lcb + u * 4], Qb + (size_t)(q0 + lrow) * HD_ + lcb + u * 4);
        cp16(&Kt[lrow][lcb + u * 4], Kb + (size_t)(n0 + lrow) * HD_ + lcb + u * 4);
    }
    cpcommit();

    float acc[2][8][4];
#pragma unroll
    for (int i = 0; i < 2; i++)
#pragma unroll
        for (int j = 0; j < 8; j++)
#pragma unroll
            for (int r = 0; r < 4; r++) acc[i][j][r] = 0.f;

    cpwait0();
    __syncthreads();

#pragma unroll
    for (int kk = 0; kk < 64; kk += 8) {
        unsigned af[2][4], bf[8][2];
#pragma unroll
        for (int i = 0; i < 2; i++) {
            const int mb = wr * 32 + i * 16;
            af[i][0] = Qt[mb + gm    ][kk + kq];
            af[i][1] = Qt[mb + gm + 8][kk + kq];
            af[i][2] = Qt[mb + gm    ][kk + kq + 4];
            af[i][3] = Qt[mb + gm + 8][kk + kq + 4];
        }
#pragma unroll
        for (int j = 0; j < 8; j++) {
            const int nb = wc * 64 + j * 8;
            bf[j][0] = Kt[nb + gm][kk + kq];
            bf[j][1] = Kt[nb + gm][kk + kq + 4];
        }
#pragma unroll
        for (int i = 0; i < 2; i++)
#pragma unroll
            for (int j = 0; j < 8; j++) mma8(acc[i][j], af[i], bf[j]);
    }

    // stage mask tile into smem (Qt/Kt dead now) with coalesced 16B loads
    __syncthreads();
    {
        const unsigned char* mg = mask + (size_t)b * L_ * L_
                                 + (size_t)(q0 + (tid >> 1)) * L_ + n0 + (tid & 1) * 64;
        unsigned char* msrow = msk + (tid >> 1) * 128 + (tid & 1) * 64;
#pragma unroll
        for (int u = 0; u < 4; u++)
            cp16(msrow + u * 16, mg + u * 16);
    }
    cpcommit(); cpwait0();
    __syncthreads();

    float* outb = att + (size_t)(h * B_ + b) * L_ * L_;

    // e = exp(s/8) (masked -> 0), write raw e, keep in acc for row sums
#pragma unroll
    for (int i = 0; i < 2; i++)
#pragma unroll
        for (int j = 0; j < 8; j++) {
            const int ql = wr * 32 + i * 16 + gm;
            const int kl = wc * 64 + j * 8 + kq * 2;
            acc[i][j][0] = msk[ql * 128 + kl]           ? 0.f : __expf(acc[i][j][0] * 0.125f);
            acc[i][j][1] = msk[ql * 128 + kl + 1]       ? 0.f : __expf(acc[i][j][1] * 0.125f);
            acc[i][j][2] = msk[(ql + 8) * 128 + kl]     ? 0.f : __expf(acc[i][j][2] * 0.125f);
            acc[i][j][3] = msk[(ql + 8) * 128 + kl + 1] ? 0.f : __expf(acc[i][j][3] * 0.125f);
            *(float2*)(outb + (size_t)(q0 + ql) * L_ + n0 + kl) =
                make_float2(acc[i][j][0], acc[i][j][1]);
            *(float2*)(outb + (size_t)(q0 + ql + 8) * L_ + n0 + kl) =
                make_float2(acc[i][j][2], acc[i][j][3]);
        }

    // per-tile row expsums: per-thread, quad shuffle, cross-warp-col combine
#pragma unroll
    for (int i = 0; i < 2; i++) {
        float s0 = 0.f, s1 = 0.f;
#pragma unroll
        for (int j = 0; j < 8; j++) {
            s0 += acc[i][j][0] + acc[i][j][1];
            s1 += acc[i][j][2] + acc[i][j][3];
        }
#pragma unroll
        for (int off = 1; off <= 2; off <<= 1) {
            s0 += __shfl_xor_sync(0xffffffffu, s0, off);
            s1 += __shfl_xor_sync(0xffffffffu, s1, off);
        }
        if (kq == 0) {
            const int r0 = wr * 32 + i * 16 + gm;
            ps[wc][r0] = s0;
            ps[wc][r0 + 8] = s1;
        }
    }
    __syncthreads();
    if (tid < 128)
        part[((size_t)bh * 16 + blockIdx.x) * L_ + q0 + tid] = ps[0][tid] + ps[1][tid];
}

// ====== fused PV: invS from partials; p = rndtf(e*invS) -> att + smem; AO = p@V ===
// BK=64, double buffered.
#define PTS 68
#define VTS 72
#define PV_SMEM ((2 * 128 * PTS + 2 * 64 * VTS) * 4)

__global__ __launch_bounds__(256, 2) void pv_tf32(
    float* __restrict__ att, const float* __restrict__ Vs,
    const float* __restrict__ part, float* __restrict__ AO)
{
    extern __shared__ unsigned sm[];
    unsigned (*Pt)[128][PTS] = (unsigned(*)[128][PTS])sm;
    unsigned (*Vt)[64][VTS]  = (unsigned(*)[64][VTS])(sm + 2 * 128 * PTS);
    __shared__ float sInv[128];

    const int tid  = threadIdx.x;
    const int lane = tid & 31, warp = tid >> 5;
    const int wr = warp >> 1, wc = warp & 1;
    const int gm = lane >> 2, kq = lane & 3;
    const int bh = blockIdx.y;                  // b*16 + h
    const int b = bh >> 4, h = bh & 15;
    const int q0 = blockIdx.x * 128;

    float* Pb = att + (size_t)(h * B_ + b) * L_ * L_;
    const float* Vb = Vs + (size_t)b * L_ * HD_ + (size_t)h * DK_;
    const int prow = tid >> 1, pcb = (tid & 1) * 32;
    const int vrow = tid >> 2, vcb = (tid & 3) * 16;

    float acc[2][4][4];
#pragma unroll
    for (int i = 0; i < 2; i++)
#pragma unroll
        for (int j = 0; j < 4; j++)
#pragma unroll
            for (int r = 0; r < 4; r++) acc[i][j][r] = 0.f;

    auto load = [&](int buf, int k0) {
#pragma unroll
        for (int u = 0; u < 8; u++)
            cp16(&Pt[buf][prow][pcb + u * 4],
                 Pb + (size_t)(q0 + prow) * L_ + k0 + pcb + u * 4);
#pragma unroll
        for (int u = 0; u < 4; u++)
            cp16(&Vt[buf][vrow][vcb + u * 4],
                 Vb + (size_t)(k0 + vrow) * HD_ + vcb + u * 4);
    };

    load(0, 0); cpcommit();

    // prologue: per-row invS from the 16 per-tile partial expsums
    if (tid < 128) {
        float s = 0.f;
#pragma unroll
        for (int t = 0; t < 16; t++)
            s += part[((size_t)bh * 16 + t) * L_ + q0 + tid];
        sInv[tid] = 1.0f / s;
    }

    int buf = 0;
    for (int k0 = 0; k0 < L_; k0 += 64) {
        cpwait0();
        __syncthreads();
        if (k0 + 64 < L_) { load(buf ^ 1, k0 + 64); cpcommit(); }

        // scale e -> p (RNA-rounded), store back to smem AND to att (final output)
        {
            const float inv = sInv[prow];
            float* psm = (float*)&Pt[buf][prow][pcb];
            float* pgm = Pb + (size_t)(q0 + prow) * L_ + k0 + pcb;
#pragma unroll
            for (int u = 0; u < 8; u++) {
                float4 v = *(float4*)(psm + u * 4);
                v.x = rndtf(v.x * inv);
                v.y = rndtf(v.y * inv);
                v.z = rndtf(v.z * inv);
                v.w = rndtf(v.w * inv);
                *(float4*)(psm + u * 4) = v;
                *(float4*)(pgm + u * 4) = v;
            }
        }
        __syncthreads();

#pragma unroll
        for (int kk = 0; kk < 64; kk += 8) {
            unsigned af[2][4], bf[4][2];
#pragma unroll
            for (int i = 0; i < 2; i++) {
                const int mb = wr * 32 + i * 16;
                af[i][0] = Pt[buf][mb + gm    ][kk + kq];
                af[i][1] = Pt[buf][mb + gm + 8][kk + kq];
                af[i][2] = Pt[buf][mb + gm    ][kk + kq + 4];
                af[i][3] = Pt[buf][mb + gm + 8][kk + kq + 4];
            }
#pragma unroll
            for (int j = 0; j < 4; j++) {
                const int nb = wc * 32 + j * 8;
                bf[j][0] = Vt[buf][kk + kq    ][nb + gm];
                bf[j][1] = Vt[buf][kk + kq + 4][nb + gm];
            }
#pragma unroll
            for (int i = 0; i < 2; i++)
#pragma unroll
                for (int j = 0; j < 4; j++) mma8(acc[i][j], af[i], bf[j]);
        }
        __syncthreads();
        buf ^= 1;
    }

#pragma unroll
    for (int i = 0; i < 2; i++)
#pragma unroll
        for (int j = 0; j < 4; j++) {
            const int q = q0 + wr * 32 + i * 16 + gm;
            const int col = wc * 32 + j * 8 + kq * 2;
            float2 o0, o1;
            o0.x = rndtf(acc[i][j][0]); o0.y = rndtf(acc[i][j][1]);
            o1.x = rndtf(acc[i][j][2]); o1.y = rndtf(acc[i][j][3]);
            *(float2*)(AO + (size_t)(b * L_ + q) * HD_ + h * DK_ + col)      = o0;
            *(float2*)(AO + (size_t)(b * L_ + q + 8) * HD_ + h * DK_ + col) = o1;
        }
}

// ---------------- residual + LayerNorm: y = LN(X + Q)*gamma + beta ---------------
__global__ __launch_bounds__(256) void ln_kernel(
    const float* __restrict__ X, const float* __restrict__ Qin,
    const float* __restrict__ gamma, const float* __restrict__ beta,
    float* __restrict__ y)
{
    __shared__ float red[8];
    const int row = blockIdx.x;
    const int tid = threadIdx.x;
    const float* xr = X + (size_t)row * DX_;
    const float* qr = Qin + (size_t)row * DX_;

    float x[4];
#pragma unroll
    for (int i = 0; i < 4; i++) x[i] = xr[tid + 256 * i] + qr[tid + 256 * i];

    float s = x[0] + x[1] + x[2] + x[3];
#pragma unroll
    for (int o = 16; o; o >>= 1) s += __shfl_xor_sync(0xffffffffu, s, o);
    if ((tid & 31) == 0) red[tid >> 5] = s;
    __syncthreads();
    s = red[0];
#pragma unroll
    for (int w = 1; w < 8; w++) s += red[w];
    const float mu = s * (1.0f / DX_);
    __syncthreads();

    float vs = 0.f;
#pragma unroll
    for (int i = 0; i < 4; i++) { float d = x[i] - mu; vs += d * d; }
#pragma unroll
    for (int o = 16; o; o >>= 1) vs += __shfl_xor_sync(0xffffffffu, vs, o);
    if ((tid & 31) == 0) red[tid >> 5] = vs;
    __syncthreads();
    vs = red[0];
#pragma unroll
    for (int w = 1; w < 8; w++) vs += red[w];
    const float var = vs * (1.0f / DX_);
    const float rs = rsqrtf(var + EPS_);

#pragma unroll
    for (int i = 0; i < 4; i++) {
        const int c = tid + 256 * i;
        y[(size_t)row * DX_ + c] = (x[i] - mu) * rs * gamma[c] + beta[c];
    }
}

// --------------------------------- launch ---------------------------------------
extern "C" void kernel_launch(void* const* d_in, const int* in_sizes, int n_in,
                              void* d_out, int out_size)
{
    const float* Q  = (const float*)d_in[0];
    const float* K  = (const float*)d_in[1];
    const float* V  = (const float*)d_in[2];
    const unsigned char* mask = (const unsigned char*)d_in[3];
    const float* Wq = (const float*)d_in[4];
    const float* bq = (const float*)d_in[5];
    const float* Wk = (const float*)d_in[6];
    const float* bk = (const float*)d_in[7];
    const float* Wv = (const float*)d_in[8];
    const float* bv = (const float*)d_in[9];
    const float* Wo = (const float*)d_in[10];
    const float* bo = (const float*)d_in[11];
    const float* gamma = (const float*)d_in[12];
    const float* beta  = (const float*)d_in[13];

    float* y   = (float*)d_out;
    float* att = (float*)d_out + (size_t)B_ * L_ * DX_;

    static float *pQs=nullptr,*pKs=nullptr,*pVs=nullptr,*pAO=nullptr,*pX=nullptr;
    static float *prWq=nullptr,*prWk=nullptr,*prWv=nullptr,*prWo=nullptr;
    static float *pPart=nullptr;
    static cudaStream_t s1, s2, s3;
    static cudaEvent_t evS, ev1, ev2, ev3;
    if (!pQs) {
        cudaGetSymbolAddress((void**)&pQs, g_Qs);
        cudaGetSymbolAddress((void**)&pKs, g_Ks);
        cudaGetSymbolAddress((void**)&pVs, g_Vs);
        cudaGetSymbolAddress((void**)&pAO, g_AO);
        cudaGetSymbolAddress((void**)&pX,  g_X);
        cudaGetSymbolAddress((void**)&prWq, g_rWq);
        cudaGetSymbolAddress((void**)&prWk, g_rWk);
        cudaGetSymbolAddress((void**)&prWv, g_rWv);
        cudaGetSymbolAddress((void**)&prWo, g_rWo);
        cudaGetSymbolAddress((void**)&pPart, g_part);
        cudaFuncSetAttribute(scores_tf32, cudaFuncAttributeMaxDynamicSharedMemorySize,
                             2 * 128 * SCS * 4);
        cudaFuncSetAttribute(pv_tf32, cudaFuncAttributeMaxDynamicSharedMemorySize,
                             PV_SMEM);
        cudaFuncSetAttribute(sgemm_tf32<true>,
                             cudaFuncAttributeMaxDynamicSharedMemorySize, SG_SMEM);
        cudaFuncSetAttribute(sgemm_tf32<false>,
                             cudaFuncAttributeMaxDynamicSharedMemorySize, SG_SMEM);
        cudaStreamCreateWithFlags(&s1, cudaStreamNonBlocking);
        cudaStreamCreateWithFlags(&s2, cudaStreamNonBlocking);
        cudaStreamCreateWithFlags(&s3, cudaStreamNonBlocking);
        cudaEventCreateWithFlags(&evS, cudaEventDisableTiming);
        cudaEventCreateWithFlags(&ev1, cudaEventDisableTiming);
        cudaEventCreateWithFlags(&ev2, cudaEventDisableTiming);
        cudaEventCreateWithFlags(&ev3, cudaEventDisableTiming);
    }

    const int nW = DX_ * HD_ / 4;                   // float4 count for a weight matrix
    const dim3 gProj(HD_ / 128, (B_ * L_) / 128);   // (8, 64)

    // fork
    cudaEventRecord(evS, 0);
    cudaStreamWaitEvent(s1, evS, 0);
    cudaStreamWaitEvent(s2, evS, 0);
    cudaStreamWaitEvent(s3, evS, 0);

    // s1: K chain (joins before scores)
    round_tf32<<<nW / 256, 256, 0, s1>>>((const float4*)Wk, (float4*)prWk, nW);
    sgemm_tf32<true><<<gProj, 256, SG_SMEM, s1>>>(K, prWk, bk, pKs, B_ * L_, HD_, DX_);
    cudaEventRecord(ev1, s1);

    // s2: V chain (joins before pv — overlaps scores)
    round_tf32<<<nW / 256, 256, 0, s2>>>((const float4*)Wv, (float4*)prWv, nW);
    sgemm_tf32<true><<<gProj, 256, SG_SMEM, s2>>>(V, prWv, bv, pVs, B_ * L_, HD_, DX_);
    cudaEventRecord(ev2, s2);

    // s3: Wo prep (joins before output projection)
    round_tf32<<<nW / 256, 256, 0, s3>>>((const float4*)Wo, (float4*)prWo, nW);
    cudaEventRecord(ev3, s3);

    // main: Q chain -> attention
    round_tf32<<<nW / 256, 256>>>((const float4*)Wq, (float4*)prWq, nW);
    sgemm_tf32<true><<<gProj, 256, SG_SMEM>>>(Q, prWq, bq, pQs, B_ * L_, HD_, DX_);

    cudaStreamWaitEvent(0, ev1, 0);
    scores_tf32<<<dim3(L_ / 128, L_ / 128, B_ * H_), 256, 2 * 128 * SCS * 4>>>(
        pQs, pKs, mask, att, pPart);

    cudaStreamWaitEvent(0, ev2, 0);
    pv_tf32<<<dim3(L_ / 128, B_ * H_), 256, PV_SMEM>>>(att, pVs, pPart, pAO);

    cudaStreamWaitEvent(0, ev3, 0);
    sgemm_tf32<false><<<gProj, 256, SG_SMEM>>>(pAO, prWo, bo, pX, B_ * L_, DX_, HD_);
    ln_kernel<<<B_ * L_, 256>>>(pX, Q, gamma, beta, y);
}

// round 14
// speedup vs baseline: 1.2119x; 1.2119x over previous
#include <cuda_runtime.h>
#include <math.h>
#include <stdint.h>

#define B_   4
#define L_   2048
#define DX_  1024
#define H_   16
#define DK_  64
#define HD_  1024      // H*DK
#define EPS_ 1e-5f

// ---------------- scratch (device globals; no allocation allowed) ----------------
__device__ float g_Qs[(size_t)B_ * L_ * HD_];
__device__ float g_Ks[(size_t)B_ * L_ * HD_];
__device__ float g_Vs[(size_t)B_ * L_ * HD_];
__device__ float g_AO[(size_t)B_ * L_ * HD_];
__device__ float g_X [(size_t)B_ * L_ * DX_];
__device__ float g_rWq[(size_t)DX_ * HD_];   // tf32-rounded weights, [K][N] layout
__device__ float g_rWk[(size_t)DX_ * HD_];
__device__ float g_rWv[(size_t)DX_ * HD_];
__device__ float g_rWo[(size_t)HD_ * DX_];
__device__ float g_part[(size_t)B_ * H_ * 16 * L_];  // (b*16+h, k-tile, row): expsum partial

// ---------------- tf32 / cp.async helpers ----------------------------------------
__device__ __forceinline__ unsigned f2tf(float x) {
    unsigned r; asm("cvt.rna.tf32.f32 %0, %1;" : "=r"(r) : "f"(x)); return r;
}
__device__ __forceinline__ float rndtf(float x) { return __uint_as_float(f2tf(x)); }

__device__ __forceinline__ void cp16(void* s, const void* g) {
    unsigned a = (unsigned)__cvta_generic_to_shared(s);
    asm volatile("cp.async.cg.shared.global [%0], [%1], 16;" :: "r"(a), "l"(g));
}
__device__ __forceinline__ void cpcommit() {
    asm volatile("cp.async.commit_group;" ::: "memory");
}
__device__ __forceinline__ void cpwait0() {
    asm volatile("cp.async.wait_group 0;" ::: "memory");
}
__device__ __forceinline__ void cpwait1() {
    asm volatile("cp.async.wait_group 1;" ::: "memory");
}
__device__ __forceinline__ void stg_cs4(float* g, float4 v) {
    asm volatile("st.global.cs.v4.f32 [%0], {%1,%2,%3,%4};"
                 :: "l"(g), "f"(v.x), "f"(v.y), "f"(v.z), "f"(v.w) : "memory");
}

__device__ __forceinline__ void mma8(float* d, const unsigned* a, const unsigned* b) {
    asm volatile(
        "mma.sync.aligned.m16n8k8.row.col.f32.tf32.tf32.f32 "
        "{%0,%1,%2,%3},{%4,%5,%6,%7},{%8,%9},{%0,%1,%2,%3};"
        : "+f"(d[0]), "+f"(d[1]), "+f"(d[2]), "+f"(d[3])
        : "r"(a[0]), "r"(a[1]), "r"(a[2]), "r"(a[3]), "r"(b[0]), "r"(b[1]));
}

// ---------------- pre-round weights to tf32 --------------------------------------
__global__ __launch_bounds__(256) void round_tf32(
    const float4* __restrict__ in, float4* __restrict__ out, int n4)
{
    int i = blockIdx.x * blockDim.x + threadIdx.x;
    if (i < n4) {
        float4 v = in[i];
        v.x = rndtf(v.x); v.y = rndtf(v.y); v.z = rndtf(v.z); v.w = rndtf(v.w);
        out[i] = v;
    }
}

// ================= TF32 SGEMM: C[M,N] = A[M,K] @ B[K,N] + bias ===================
// A is RAW fp32 (rounded to tf32 in-register at fragment load); B is pre-rounded.
// BK=16 double buffered; prefetch issued BEFORE wait (wait_group 1).
template<bool ROUND_OUT>
__global__ __launch_bounds__(256, 2) void sgemm_tf32(
    const float* __restrict__ A, const float* __restrict__ Bm,
    const float* __restrict__ bias, float* __restrict__ C,
    int M, int N, int K)
{
    __shared__ unsigned As[2][128][20];
    __shared__ unsigned Bs[2][16][136];
    const int tid  = threadIdx.x;
    const int lane = tid & 31, warp = tid >> 5;
    const int wr = warp >> 1, wc = warp & 1;
    const int gm = lane >> 2, kq = lane & 3;

    const float* Ab = A  + (size_t)(blockIdx.y * 128) * K;
    const float* Bb = Bm + blockIdx.x * 128;
    const int arow = tid >> 1,  acol = (tid & 1) * 8;
    const int brow = tid >> 4,  bcol = (tid & 15) * 8;

    float acc[2][8][4];
#pragma unroll
    for (int i = 0; i < 2; i++)
#pragma unroll
        for (int j = 0; j < 8; j++)
#pragma unroll
            for (int r = 0; r < 4; r++) acc[i][j][r] = 0.f;

    auto load = [&](int buf, int k0) {
        cp16(&As[buf][arow][acol],     Ab + (size_t)arow * K + k0 + acol);
        cp16(&As[buf][arow][acol + 4], Ab + (size_t)arow * K + k0 + acol + 4);
        cp16(&Bs[buf][brow][bcol],     Bb + (size_t)(k0 + brow) * N + bcol);
        cp16(&Bs[buf][brow][bcol + 4], Bb + (size_t)(k0 + brow) * N + bcol + 4);
    };

    load(0, 0); cpcommit();
    int buf = 0;
    for (int k0 = 0; k0 < K; k0 += 16) {
        if (k0 + 16 < K) { load(buf ^ 1, k0 + 16); cpcommit(); cpwait1(); }
        else             { cpwait0(); }
        __syncthreads();
#pragma unroll
        for (int kk = 0; kk < 16; kk += 8) {
            unsigned af[2][4], bf[8][2];
#pragma unroll
            for (int i = 0; i < 2; i++) {
                const int mb = wr * 32 + i * 16;
                af[i][0] = f2tf(__uint_as_float(As[buf][mb + gm    ][kk + kq]));
                af[i][1] = f2tf(__uint_as_float(As[buf][mb + gm + 8][kk + kq]));
                af[i][2] = f2tf(__uint_as_float(As[buf][mb + gm    ][kk + kq + 4]));
                af[i][3] = f2tf(__uint_as_float(As[buf][mb + gm + 8][kk + kq + 4]));
            }
#pragma unroll
            for (int j = 0; j < 8; j++) {
                const int nb = wc * 64 + j * 8;
                bf[j][0] = Bs[buf][kk + kq    ][nb + gm];
                bf[j][1] = Bs[buf][kk + kq + 4][nb + gm];
            }
#pragma unroll
            for (int i = 0; i < 2; i++)
#pragma unroll
                for (int j = 0; j < 8; j++) mma8(acc[i][j], af[i], bf[j]);
        }
        __syncthreads();
        buf ^= 1;
    }

#pragma unroll
    for (int i = 0; i < 2; i++)
#pragma unroll
        for (int j = 0; j < 8; j++) {
            const int row = blockIdx.y * 128 + wr * 32 + i * 16 + gm;
            const int col = blockIdx.x * 128 + wc * 64 + j * 8 + kq * 2;
            float2 bv = *(const float2*)(bias + col);
            float2 o0, o1;
            o0.x = acc[i][j][0] + bv.x; o0.y = acc[i][j][1] + bv.y;
            o1.x = acc[i][j][2] + bv.x; o1.y = acc[i][j][3] + bv.y;
            if (ROUND_OUT) {
                o0.x = rndtf(o0.x); o0.y = rndtf(o0.y);
                o1.x = rndtf(o1.x); o1.y = rndtf(o1.y);
            }
            *(float2*)(C + (size_t)row * N + col)       = o0;
            *(float2*)(C + (size_t)(row + 8) * N + col) = o1;
        }
}

// ===== scores: e = exp((Qh@Kh^T)/8) masked->0; writes e + per-tile row expsums ====
#define SCS 68
__global__ __launch_bounds__(256, 2) void scores_tf32(
    const float* __restrict__ Qs, const float* __restrict__ Ks,
    const unsigned char* __restrict__ mask, float* __restrict__ att,
    float* __restrict__ part)
{
    extern __shared__ unsigned sm[];
    unsigned (*Qt)[SCS] = (unsigned(*)[SCS])sm;
    unsigned (*Kt)[SCS] = (unsigned(*)[SCS])(sm + 128 * SCS);
    unsigned char* msk = (unsigned char*)sm;     // reused after mainloop
    __shared__ float ps[2][128];

    const int tid  = threadIdx.x;
    const int lane = tid & 31, warp = tid >> 5;
    const int wr = warp >> 1, wc = warp & 1;
    const int gm = lane >> 2, kq = lane & 3;
    const int bh = blockIdx.z;                  // b*16 + h
    const int b = bh >> 4, h = bh & 15;
    const int q0 = blockIdx.y * 128, n0 = blockIdx.x * 128;

    const float* Qb = Qs + (size_t)b * L_ * HD_ + (size_t)h * DK_;
    const float* Kb = Ks + (size_t)b * L_ * HD_ + (size_t)h * DK_;
    const int lrow = tid >> 1, lcb = (tid & 1) * 32;

#pragma unroll
    for (int u = 0; u < 8; u++) {
        cp16(&Qt[lrow][lcb + u * 4], Qb + (size_t)(q0 + lrow) * HD_ + lcb + u * 4);
        cp16(&Kt[lrow][lcb + u * 4], Kb + (size_t)(n0 + lrow) * HD_ + lcb + u * 4);
    }
    cpcommit();

    float acc[2][8][4];
#pragma unroll
    for (int i = 0; i < 2; i++)
#pragma unroll
        for (int j = 0; j < 8; j++)
#pragma unroll
            for (int r = 0; r < 4; r++) acc[i][j][r] = 0.f;

    cpwait0();
    __syncthreads();

#pragma unroll
    for (int kk = 0; kk < 64; kk += 8) {
        unsigned af[2][4], bf[8][2];
#pragma unroll
        for (int i = 0; i < 2; i++) {
            const int mb = wr * 32 + i * 16;
            af[i][0] = Qt[mb + gm    ][kk + kq];
            af[i][1] = Qt[mb + gm + 8][kk + kq];
            af[i][2] = Qt[mb + gm    ][kk + kq + 4];
            af[i][3] = Qt[mb + gm + 8][kk + kq + 4];
        }
#pragma unroll
        for (int j = 0; j < 8; j++) {
            const int nb = wc * 64 + j * 8;
            bf[j][0] = Kt[nb + gm][kk + kq];
            bf[j][1] = Kt[nb + gm][kk + kq + 4];
        }
#pragma unroll
        for (int i = 0; i < 2; i++)
#pragma unroll
            for (int j = 0; j < 8; j++) mma8(acc[i][j], af[i], bf[j]);
    }

    // stage mask tile into smem (Qt/Kt dead now) with coalesced 16B loads
    __syncthreads();
    {
        const unsigned char* mg = mask + (size_t)b * L_ * L_
                                 + (size_t)(q0 + (tid >> 1)) * L_ + n0 + (tid & 1) * 64;
        unsigned char* msrow = msk + (tid >> 1) * 128 + (tid & 1) * 64;
#pragma unroll
        for (int u = 0; u < 4; u++)
            cp16(msrow + u * 16, mg + u * 16);
    }
    cpcommit(); cpwait0();
    __syncthreads();

    float* outb = att + (size_t)(h * B_ + b) * L_ * L_;

    // e = exp(s/8) (masked -> 0), write raw e, keep in acc for row sums
#pragma unroll
    for (int i = 0; i < 2; i++)
#pragma unroll
        for (int j = 0; j < 8; j++) {
            const int ql = wr * 32 + i * 16 + gm;
            const int kl = wc * 64 + j * 8 + kq * 2;
            acc[i][j][0] = msk[ql * 128 + kl]           ? 0.f : __expf(acc[i][j][0] * 0.125f);
            acc[i][j][1] = msk[ql * 128 + kl + 1]       ? 0.f : __expf(acc[i][j][1] * 0.125f);
            acc[i][j][2] = msk[(ql + 8) * 128 + kl]     ? 0.f : __expf(acc[i][j][2] * 0.125f);
            acc[i][j][3] = msk[(ql + 8) * 128 + kl + 1] ? 0.f : __expf(acc[i][j][3] * 0.125f);
            *(float2*)(outb + (size_t)(q0 + ql) * L_ + n0 + kl) =
                make_float2(acc[i][j][0], acc[i][j][1]);
            *(float2*)(outb + (size_t)(q0 + ql + 8) * L_ + n0 + kl) =
                make_float2(acc[i][j][2], acc[i][j][3]);
        }

    // per-tile row expsums: per-thread, quad shuffle, cross-warp-col combine
#pragma unroll
    for (int i = 0; i < 2; i++) {
        float s0 = 0.f, s1 = 0.f;
#pragma unroll
        for (int j = 0; j < 8; j++) {
            s0 += acc[i][j][0] + acc[i][j][1];
            s1 += acc[i][j][2] + acc[i][j][3];
        }
#pragma unroll
        for (int off = 1; off <= 2; off <<= 1) {
            s0 += __shfl_xor_sync(0xffffffffu, s0, off);
            s1 += __shfl_xor_sync(0xffffffffu, s1, off);
        }
        if (kq == 0) {
            const int r0 = wr * 32 + i * 16 + gm;
            ps[wc][r0] = s0;
            ps[wc][r0 + 8] = s1;
        }
    }
    __syncthreads();
    if (tid < 128)
        part[((size_t)bh * 16 + blockIdx.x) * L_ + q0 + tid] = ps[0][tid] + ps[1][tid];
}

// ====== fused PV: invS from partials; p = rndtf(e*invS) -> att + smem; AO = p@V ===
// BK=32 double buffered; prefetch issued BEFORE wait (wait_group 1).
#define PTS 36
#define VTS 72
#define PV_SMEM ((2 * 128 * PTS + 2 * 32 * VTS) * 4)

__global__ __launch_bounds__(256, 2) void pv_tf32(
    float* __restrict__ att, const float* __restrict__ Vs,
    const float* __restrict__ part, float* __restrict__ AO)
{
    extern __shared__ unsigned sm[];
    unsigned (*Pt)[128][PTS] = (unsigned(*)[128][PTS])sm;
    unsigned (*Vt)[32][VTS]  = (unsigned(*)[32][VTS])(sm + 2 * 128 * PTS);
    __shared__ float sInv[128];

    const int tid  = threadIdx.x;
    const int lane = tid & 31, warp = tid >> 5;
    const int wr = warp >> 1, wc = warp & 1;
    const int gm = lane >> 2, kq = lane & 3;
    const int bh = blockIdx.y;                  // b*16 + h
    const int b = bh >> 4, h = bh & 15;
    const int q0 = blockIdx.x * 128;

    float* Pb = att + (size_t)(h * B_ + b) * L_ * L_;
    const float* Vb = Vs + (size_t)b * L_ * HD_ + (size_t)h * DK_;
    const int prow = tid >> 1, pcb = (tid & 1) * 16;
    const int vrow = tid >> 3, vcb = (tid & 7) * 8;

    float acc[2][4][4];
#pragma unroll
    for (int i = 0; i < 2; i++)
#pragma unroll
        for (int j = 0; j < 4; j++)
#pragma unroll
            for (int r = 0; r < 4; r++) acc[i][j][r] = 0.f;

    auto load = [&](int buf, int k0) {
#pragma unroll
        for (int u = 0; u < 4; u++)
            cp16(&Pt[buf][prow][pcb + u * 4],
                 Pb + (size_t)(q0 + prow) * L_ + k0 + pcb + u * 4);
#pragma unroll
        for (int u = 0; u < 2; u++)
            cp16(&Vt[buf][vrow][vcb + u * 4],
                 Vb + (size_t)(k0 + vrow) * HD_ + vcb + u * 4);
    };

    load(0, 0); cpcommit();

    // prologue: per-row invS from the 16 per-tile partial expsums
    if (tid < 128) {
        float s = 0.f;
#pragma unroll
        for (int t = 0; t < 16; t++)
            s += part[((size_t)bh * 16 + t) * L_ + q0 + tid];
        sInv[tid] = 1.0f / s;
    }

    int buf = 0;
    for (int k0 = 0; k0 < L_; k0 += 32) {
        if (k0 + 32 < L_) { load(buf ^ 1, k0 + 32); cpcommit(); cpwait1(); }
        else              { cpwait0(); }
        __syncthreads();

        // scale e -> p (RNA-rounded), store to smem + streaming store to att
        {
            const float inv = sInv[prow];
            float* psm = (float*)&Pt[buf][prow][pcb];
            float* pgm = Pb + (size_t)(q0 + prow) * L_ + k0 + pcb;
#pragma unroll
            for (int u = 0; u < 4; u++) {
                float4 v = *(float4*)(psm + u * 4);
                v.x = rndtf(v.x * inv);
                v.y = rndtf(v.y * inv);
                v.z = rndtf(v.z * inv);
                v.w = rndtf(v.w * inv);
                *(float4*)(psm + u * 4) = v;
                stg_cs4(pgm + u * 4, v);
            }
        }
        __syncthreads();

#pragma unroll
        for (int kk = 0; kk < 32; kk += 8) {
            unsigned af[2][4], bf[4][2];
#pragma unroll
            for (int i = 0; i < 2; i++) {
                const int mb = wr * 32 + i * 16;
                af[i][0] = Pt[buf][mb + gm    ][kk + kq];
                af[i][1] = Pt[buf][mb + gm + 8][kk + kq];
                af[i][2] = Pt[buf][mb + gm    ][kk + kq + 4];
                af[i][3] = Pt[buf][mb + gm + 8][kk + kq + 4];
            }
#pragma unroll
            for (int j = 0; j < 4; j++) {
                const int nb = wc * 32 + j * 8;
                bf[j][0] = Vt[buf][kk + kq    ][nb + gm];
                bf[j][1] = Vt[buf][kk + kq + 4][nb + gm];
            }
#pragma unroll
            for (int i = 0; i < 2; i++)
#pragma unroll
                for (int j = 0; j < 4; j++) mma8(acc[i][j], af[i], bf[j]);
        }
        __syncthreads();
        buf ^= 1;
    }

#pragma unroll
    for (int i = 0; i < 2; i++)
#pragma unroll
        for (int j = 0; j < 4; j++) {
            const int q = q0 + wr * 32 + i * 16 + gm;
            const int col = wc * 32 + j * 8 + kq * 2;
            float2 o0, o1;
            o0.x = rndtf(acc[i][j][0]); o0.y = rndtf(acc[i][j][1]);
            o1.x = rndtf(acc[i][j][2]); o1.y = rndtf(acc[i][j][3]);
            *(float2*)(AO + (size_t)(b * L_ + q) * HD_ + h * DK_ + col)      = o0;
            *(float2*)(AO + (size_t)(b * L_ + q + 8) * HD_ + h * DK_ + col) = o1;
        }
}

// ---------------- residual + LayerNorm: y = LN(X + Q)*gamma + beta ---------------
__global__ __launch_bounds__(256) void ln_kernel(
    const float* __restrict__ X, const float* __restrict__ Qin,
    const float* __restrict__ gamma, const float* __restrict__ beta,
    float* __restrict__ y)
{
    __shared__ float red[8];
    const int row = blockIdx.x;
    const int tid = threadIdx.x;
    const float* xr = X + (size_t)row * DX_;
    const float* qr = Qin + (size_t)row * DX_;

    float x[4];
#pragma unroll
    for (int i = 0; i < 4; i++) x[i] = xr[tid + 256 * i] + qr[tid + 256 * i];

    float s = x[0] + x[1] + x[2] + x[3];
#pragma unroll
    for (int o = 16; o; o >>= 1) s += __shfl_xor_sync(0xffffffffu, s, o);
    if ((tid & 31) == 0) red[tid >> 5] = s;
    __syncthreads();
    s = red[0];
#pragma unroll
    for (int w = 1; w < 8; w++) s += red[w];
    const float mu = s * (1.0f / DX_);
    __syncthreads();

    float vs = 0.f;
#pragma unroll
    for (int i = 0; i < 4; i++) { float d = x[i] - mu; vs += d * d; }
#pragma unroll
    for (int o = 16; o; o >>= 1) vs += __shfl_xor_sync(0xffffffffu, vs, o);
    if ((tid & 31) == 0) red[tid >> 5] = vs;
    __syncthreads();
    vs = red[0];
#pragma unroll
    for (int w = 1; w < 8; w++) vs += red[w];
    const float var = vs * (1.0f / DX_);
    const float rs = rsqrtf(var + EPS_);

#pragma unroll
    for (int i = 0; i < 4; i++) {
        const int c = tid + 256 * i;
        y[(size_t)row * DX_ + c] = (x[i] - mu) * rs * gamma[c] + beta[c];
    }
}

// --------------------------------- launch ---------------------------------------
extern "C" void kernel_launch(void* const* d_in, const int* in_sizes, int n_in,
                              void* d_out, int out_size)
{
    const float* Q  = (const float*)d_in[0];
    const float* K  = (const float*)d_in[1];
    const float* V  = (const float*)d_in[2];
    const unsigned char* mask = (const unsigned char*)d_in[3];
    const float* Wq = (const float*)d_in[4];
    const float* bq = (const float*)d_in[5];
    const float* Wk = (const float*)d_in[6];
    const float* bk = (const float*)d_in[7];
    const float* Wv = (const float*)d_in[8];
    const float* bv = (const float*)d_in[9];
    const float* Wo = (const float*)d_in[10];
    const float* bo = (const float*)d_in[11];
    const float* gamma = (const float*)d_in[12];
    const float* beta  = (const float*)d_in[13];

    float* y   = (float*)d_out;
    float* att = (float*)d_out + (size_t)B_ * L_ * DX_;

    static float *pQs=nullptr,*pKs=nullptr,*pVs=nullptr,*pAO=nullptr,*pX=nullptr;
    static float *prWq=nullptr,*prWk=nullptr,*prWv=nullptr,*prWo=nullptr;
    static float *pPart=nullptr;
    static cudaStream_t s1, s2, s3;
    static cudaEvent_t evS, ev1, ev2, ev3;
    if (!pQs) {
        cudaGetSymbolAddress((void**)&pQs, g_Qs);
        cudaGetSymbolAddress((void**)&pKs, g_Ks);
        cudaGetSymbolAddress((void**)&pVs, g_Vs);
        cudaGetSymbolAddress((void**)&pAO, g_AO);
        cudaGetSymbolAddress((void**)&pX,  g_X);
        cudaGetSymbolAddress((void**)&prWq, g_rWq);
        cudaGetSymbolAddress((void**)&prWk, g_rWk);
        cudaGetSymbolAddress((void**)&prWv, g_rWv);
        cudaGetSymbolAddress((void**)&prWo, g_rWo);
        cudaGetSymbolAddress((void**)&pPart, g_part);
        cudaFuncSetAttribute(scores_tf32, cudaFuncAttributeMaxDynamicSharedMemorySize,
                             2 * 128 * SCS * 4);
        cudaFuncSetAttribute(pv_tf32, cudaFuncAttributeMaxDynamicSharedMemorySize,
                             PV_SMEM);
        cudaStreamCreateWithFlags(&s1, cudaStreamNonBlocking);
        cudaStreamCreateWithFlags(&s2, cudaStreamNonBlocking);
        cudaStreamCreateWithFlags(&s3, cudaStreamNonBlocking);
        cudaEventCreateWithFlags(&evS, cudaEventDisableTiming);
        cudaEventCreateWithFlags(&ev1, cudaEventDisableTiming);
        cudaEventCreateWithFlags(&ev2, cudaEventDisableTiming);
        cudaEventCreateWithFlags(&ev3, cudaEventDisableTiming);
    }

    const int nW = DX_ * HD_ / 4;                   // float4 count for a weight matrix
    const dim3 gProj(HD_ / 128, (B_ * L_) / 128);   // (8, 64)

    // fork
    cudaEventRecord(evS, 0);
    cudaStreamWaitEvent(s1, evS, 0);
    cudaStreamWaitEvent(s2, evS, 0);
    cudaStreamWaitEvent(s3, evS, 0);

    // s1: K chain (joins before scores)
    round_tf32<<<nW / 256, 256, 0, s1>>>((const float4*)Wk, (float4*)prWk, nW);
    sgemm_tf32<true><<<gProj, 256, 0, s1>>>(K, prWk, bk, pKs, B_ * L_, HD_, DX_);
    cudaEventRecord(ev1, s1);

    // s2: V chain (joins before pv — overlaps scores)
    round_tf32<<<nW / 256, 256, 0, s2>>>((const float4*)Wv, (float4*)prWv, nW);
    sgemm_tf32<true><<<gProj, 256, 0, s2>>>(V, prWv, bv, pVs, B_ * L_, HD_, DX_);
    cudaEventRecord(ev2, s2);

    // s3: Wo prep (joins before output projection)
    round_tf32<<<nW / 256, 256, 0, s3>>>((const float4*)Wo, (float4*)prWo, nW);
    cudaEventRecord(ev3, s3);

    // main: Q chain -> attention
    round_tf32<<<nW / 256, 256>>>((const float4*)Wq, (float4*)prWq, nW);
    sgemm_tf32<true><<<gProj, 256>>>(Q, prWq, bq, pQs, B_ * L_, HD_, DX_);

    cudaStreamWaitEvent(0, ev1, 0);
    scores_tf32<<<dim3(L_ / 128, L_ / 128, B_ * H_), 256, 2 * 128 * SCS * 4>>>(
        pQs, pKs, mask, att, pPart);

    cudaStreamWaitEvent(0, ev2, 0);
    pv_tf32<<<dim3(L_ / 128, B_ * H_), 256, PV_SMEM>>>(att, pVs, pPart, pAO);

    cudaStreamWaitEvent(0, ev3, 0);
    sgemm_tf32<false><<<gProj, 256>>>(pAO, prWo, bo, pX, B_ * L_, DX_, HD_);
    ln_kernel<<<B_ * L_, 256>>>(pX, Q, gamma, beta, y);
}